// round 8
// baseline (speedup 1.0000x reference)
#include <cuda_runtime.h>
#include <cuda_bf16.h>
#include <math.h>

#define NN 90000
#define PRE_K 6000
#define POST_K 300
#define NW 188                    // ceil(6000/32)
#define NBINS 65536
#define CAND_CAP 8192
#define MIN_SIZE 0.02f
#define GRID 148
#define BLK 1024
#define STRIDE (GRID * BLK)
#define RS_BLOCKS 32              // rank/scatter blocks
#define CPB (CAND_CAP / RS_BLOCKS)   // 256 candidates per block
#define SEG 512                   // keys per smem tile
#define NSEGS (CAND_CAP / SEG)    // 16

// ---------------- device scratch ----------------
__device__ unsigned long long g_keys[NN];
__device__ float4             g_boxes[NN];
__device__ unsigned int       g_hist[NBINS];
__device__ unsigned long long g_cand[CAND_CAP];
__device__ int                g_cand_cnt;
__device__ float4             g_top[PRE_K + 32];
__device__ unsigned int       g_valid[NW];
__device__ unsigned int       g_barrier;

// ---------------- software grid barrier (148 blocks co-resident) ------
__device__ __forceinline__ void gsync(unsigned int target) {
    __syncthreads();
    if (threadIdx.x == 0) {
        __threadfence();
        atomicAdd(&g_barrier, 1u);
        volatile unsigned int* p = &g_barrier;
        while (*p < target) __nanosleep(32);
        __threadfence();
    }
    __syncthreads();
}

// ---------------- init kernel ----------------
__global__ void init_kernel() {
    int i = blockIdx.x * blockDim.x + threadIdx.x;
    for (int b = i; b < NBINS; b += 296 * 256) g_hist[b] = 0u;
    if (i < NW) g_valid[i] = 0u;
    if (i == 0) { g_cand_cnt = 0; g_barrier = 0u; }
}

// ---------------- mega kernel ----------------
__global__ void __launch_bounds__(BLK, 1) mega_kernel(
        const float* __restrict__ pred_cls,
        const float* __restrict__ pred_reg,
        const float* __restrict__ anchor,
        float* __restrict__ out) {
    int tid = threadIdx.x;
    int bid = blockIdx.x;
    int gtid = bid * BLK + tid;

    __shared__ union {
        struct {                                    // thresh (per-block redundant)
            unsigned int part[BLK];
            unsigned int fine[64];
            int pt;
            unsigned int acc0;
            unsigned int T;
        } th;
        unsigned long long tile[SEG];               // rank tiles
        struct {                                    // batch NMS
            float4 kbox[POST_K];
            float  karea[POST_K];
            float4 bbox[32];
            float  barea[32];
            unsigned int mrow[32];
            unsigned int supA;
            unsigned int keepm;
            unsigned int validw;
            int kept;
        } nm;
    } sm;

    // ---------- phase 1: decode ----------
    for (int n = gtid; n < NN; n += STRIDE) {
        float4 a = *(const float4*)&anchor[n * 4];
        float4 r = *(const float4*)&pred_reg[n * 4];
        float acx = (a.x + a.z) * 0.5f;
        float acy = (a.y + a.w) * 0.5f;
        float aw  = a.z - a.x;
        float ah  = a.w - a.y;
        float cx = r.x * aw + acx;
        float cy = r.y * ah + acy;
        float w  = expf(r.z) * aw;
        float h  = expf(r.w) * ah;
        float x0 = fminf(fmaxf(cx - w * 0.5f, 0.f), 1.f);
        float y0 = fminf(fmaxf(cy - h * 0.5f, 0.f), 1.f);
        float x1 = fminf(fmaxf(cx + w * 0.5f, 0.f), 1.f);
        float y1 = fminf(fmaxf(cy + h * 0.5f, 0.f), 1.f);
        g_boxes[n] = make_float4(x0, y0, x1, y1);

        float2 l = *(const float2*)&pred_cls[2 * n];
        float m  = fmaxf(l.x, l.y);
        float e0 = expf(l.x - m);
        float e1 = expf(l.y - m);
        float p  = e1 / (e0 + e1);
        bool size_ok = ((y1 - y0) >= MIN_SIZE) && ((x1 - x0) >= MIN_SIZE);
        float s = size_ok ? p : -INFINITY;
        unsigned int ub = __float_as_uint(s);
        unsigned int ordered = (ub & 0x80000000u) ? ~ub : (ub | 0x80000000u);
        unsigned long long key =
            ((unsigned long long)ordered << 17) | ((~(unsigned int)n) & 0x1FFFFu);
        g_keys[n] = key;
        atomicAdd(&g_hist[ordered >> 16], 1u);
    }
    gsync(1 * GRID);

    // ---------- phase 2: threshold (EVERY block, redundant, no barrier) ----------
    unsigned int T;
    {
        // each thread sums its 64-bin group via 16 uint4 loads
        const uint4* h4 = (const uint4*)g_hist;
        unsigned int s = 0;
        int base = tid * 16;                        // uint4 index
        #pragma unroll
        for (int b = 0; b < 16; b++) {
            uint4 v = h4[base + b];
            s += v.x + v.y + v.z + v.w;
        }
        sm.th.part[tid] = s;
        __syncthreads();
        for (int off = 1; off < BLK; off <<= 1) {   // suffix scan
            unsigned int v = (tid + off < BLK) ? sm.th.part[tid + off] : 0u;
            __syncthreads();
            sm.th.part[tid] += v;
            __syncthreads();
        }
        bool pred = sm.th.part[tid] >= (unsigned)PRE_K;
        bool next = (tid < BLK - 1) ? (sm.th.part[tid + 1] >= (unsigned)PRE_K) : false;
        if (tid == 0) { sm.th.pt = 0; sm.th.acc0 = 0u; }
        __syncthreads();
        if (pred && !next) {
            sm.th.pt = tid;
            sm.th.acc0 = (tid < BLK - 1) ? sm.th.part[tid + 1] : 0u;
        }
        __syncthreads();
        int pt = sm.th.pt;
        unsigned int acc0 = sm.th.acc0;
        if (tid < 64) sm.th.fine[tid] = g_hist[pt * 64 + tid];
        __syncthreads();
        for (int off = 1; off < 64; off <<= 1) {
            unsigned int v = (tid < 64 && tid + off < 64) ? sm.th.fine[tid + off] : 0u;
            __syncthreads();
            if (tid < 64) sm.th.fine[tid] += v;
            __syncthreads();
        }
        if (tid < 64) {
            bool fp = (acc0 + sm.th.fine[tid]) >= (unsigned)PRE_K;
            bool fn = (tid < 63) ? ((acc0 + sm.th.fine[tid + 1]) >= (unsigned)PRE_K) : false;
            if (fp && !fn) sm.th.T = (unsigned int)(pt * 64 + tid);
        }
        __syncthreads();
        T = sm.th.T;
    }

    // ---------- phase 3: compact ----------
    for (int n = gtid; n < NN; n += STRIDE) {
        unsigned long long key = g_keys[n];
        if ((unsigned int)(key >> 33) >= T) {
            int p = atomicAdd(&g_cand_cnt, 1);
            if (p < CAND_CAP) g_cand[p] = key;
        }
    }
    gsync(2 * GRID);

    // ---------- phase 4: fused rank + scatter (32 blocks) ----------
    if (bid < RS_BLOCKS) {
        int C = g_cand_cnt; if (C > CAND_CAP) C = CAND_CAP;
        int c = bid * CPB + (tid >> 2);             // candidate index
        int q = tid & 3;                            // quarter of each tile
        unsigned long long kc = (c < C) ? g_cand[c] : 0xFFFFFFFFFFFFFFFFULL;
        int cnt = 0;
        for (int seg = 0; seg < NSEGS; seg++) {
            __syncthreads();
            if (tid < SEG) {
                int gi = seg * SEG + tid;
                sm.tile[tid] = (gi < C) ? g_cand[gi] : 0ULL;
            }
            __syncthreads();
            int k0 = q * (SEG / 4);
            #pragma unroll 8
            for (int k = 0; k < SEG / 4; k++)
                cnt += (sm.tile[k0 + k] > kc);
        }
        // combine quarters (lanes 4m..4m+3)
        cnt += __shfl_down_sync(0xFFFFFFFFu, cnt, 1);
        cnt += __shfl_down_sync(0xFFFFFFFFu, cnt, 2);
        if (q == 0 && c < C && cnt < PRE_K) {
            unsigned long long key = kc;
            unsigned int idx = (~(unsigned int)key) & 0x1FFFFu;
            float4 b = (idx < NN) ? g_boxes[idx] : make_float4(0.f, 0.f, 0.f, 0.f);
            g_top[cnt] = b;
            if ((key >> 48) & 1ULL)
                atomicOr(&g_valid[cnt >> 5], 1u << (cnt & 31));
        }
    }
    gsync(3 * GRID);

    // ---------- phase 5: batched greedy NMS (block 0 only) ----------
    if (bid != 0) return;

    int lane = tid & 31;
    int wrp  = tid >> 5;

    if (tid == 0) sm.nm.kept = 0;
    __syncthreads();

    for (int c = 0; c < NW; c++) {
        int keptC = sm.nm.kept;
        if (keptC >= POST_K) break;
        int r0 = c * 32;

        if (tid < 32) {
            int r = r0 + tid;
            float4 b = (r < PRE_K) ? g_top[r] : make_float4(0.f, 0.f, 0.f, 0.f);
            sm.nm.bbox[tid]  = b;
            sm.nm.barea[tid] = (b.z - b.x) * (b.w - b.y);
        }
        if (tid == 0) {
            sm.nm.supA   = 0u;
            sm.nm.validw = g_valid[c];
        }
        __syncthreads();

        // stage A: suppression by existing kept list
        {
            float4 bj = sm.nm.bbox[lane];
            float  aj = sm.nm.barea[lane];
            bool supped = false;
            for (int k = wrp; k < keptC; k += 32) {
                float4 bk = sm.nm.kbox[k];
                float x0 = fmaxf(bk.x, bj.x);
                float y0 = fmaxf(bk.y, bj.y);
                float x1 = fminf(bk.z, bj.z);
                float y1 = fminf(bk.w, bj.w);
                float iw = fmaxf(x1 - x0, 0.f);
                float ih = fmaxf(y1 - y0, 0.f);
                float inter = iw * ih;
                float uni   = sm.nm.karea[k] + aj - inter;
                if (inter / fmaxf(uni, 1e-12f) > 0.7f) { supped = true; break; }
            }
            unsigned int bal = __ballot_sync(0xFFFFFFFFu, supped);
            if (lane == 0 && bal) atomicOr(&sm.nm.supA, bal);
        }

        // stage B: in-batch 32x32 IoU matrix
        {
            float4 bi = sm.nm.bbox[wrp];
            float  ai = sm.nm.barea[wrp];
            float4 bj = sm.nm.bbox[lane];
            float x0 = fmaxf(bi.x, bj.x);
            float y0 = fmaxf(bi.y, bj.y);
            float x1 = fminf(bi.z, bj.z);
            float y1 = fminf(bi.w, bj.w);
            float iw = fmaxf(x1 - x0, 0.f);
            float ih = fmaxf(y1 - y0, 0.f);
            float inter = iw * ih;
            float uni   = ai + sm.nm.barea[lane] - inter;
            bool bit = (inter / fmaxf(uni, 1e-12f) > 0.7f) && (lane > wrp);
            unsigned int bal = __ballot_sync(0xFFFFFFFFu, bit);
            if (lane == 0) sm.nm.mrow[wrp] = bal;
        }
        __syncthreads();

        // stage C: greedy resolve (thread 0)
        if (tid == 0) {
            unsigned int sup = sm.nm.supA | ~sm.nm.validw;
            unsigned int keepm = 0;
            #pragma unroll
            for (int i = 0; i < 32; i++) {
                if (!((sup >> i) & 1u)) {
                    keepm |= (1u << i);
                    sup |= sm.nm.mrow[i];
                }
            }
            sm.nm.keepm = keepm;
            sm.nm.kept  = keptC + __popc(keepm);
        }
        __syncthreads();

        // stage D: append kept boxes
        if (tid < 32) {
            unsigned int keepm = sm.nm.keepm;
            if ((keepm >> tid) & 1u) {
                int pos = keptC + __popc(keepm & ((1u << tid) - 1u));
                if (pos < POST_K) {
                    float4 b = sm.nm.bbox[tid];
                    sm.nm.kbox[pos]  = b;
                    sm.nm.karea[pos] = sm.nm.barea[tid];
                    ((float4*)out)[pos] = b;
                }
            }
        }
        __syncthreads();
    }

    int kept = sm.nm.kept;
    if (kept > POST_K) kept = POST_K;
    for (int idx = tid; idx < (POST_K - kept) * 4; idx += BLK)
        out[kept * 4 + idx] = 0.f;
}

// ---------------- launcher ----------------
extern "C" void kernel_launch(void* const* d_in, const int* in_sizes, int n_in,
                              void* d_out, int out_size) {
    const float* pred_cls = (const float*)d_in[0];
    const float* pred_reg = (const float*)d_in[1];
    const float* anchor   = (const float*)d_in[2];
    float* out = (float*)d_out;

    init_kernel<<<296, 256>>>();
    mega_kernel<<<GRID, BLK>>>(pred_cls, pred_reg, anchor, out);
}